// round 6
// baseline (speedup 1.0000x reference)
#include <cuda_runtime.h>
#include <cstdint>

#define BB 256
#define FF 2048
#define HH 512
#define CC 512
#define EE 8
#define HH2 256
#define BCE (BB * CC * EE)

__device__ float g_shared[BB * HH];   // [B,H] tf32-rounded activations

// ---------------------------------------------------------------------------
// helpers
// ---------------------------------------------------------------------------
__device__ __forceinline__ unsigned f2tf32(float x) {
    unsigned u; asm("cvt.rna.tf32.f32 %0, %1;" : "=r"(u) : "f"(x)); return u;
}
__device__ __forceinline__ unsigned smem_u32(const void* p) {
    return (unsigned)__cvta_generic_to_shared(p);
}
__device__ __forceinline__ void cp16(unsigned dst, const void* src) {
    asm volatile("cp.async.cg.shared.global [%0], [%1], 16;" :: "r"(dst), "l"(src));
}
__device__ __forceinline__ void mma_tf32(float* d, const unsigned* a, const unsigned* b) {
    asm volatile(
        "mma.sync.aligned.m16n8k8.row.col.f32.tf32.tf32.f32 "
        "{%0,%1,%2,%3}, {%4,%5,%6,%7}, {%8,%9}, {%0,%1,%2,%3};"
        : "+f"(d[0]), "+f"(d[1]), "+f"(d[2]), "+f"(d[3])
        : "r"(a[0]), "r"(a[1]), "r"(a[2]), "r"(a[3]), "r"(b[0]), "r"(b[1]));
}
// 4x(8 rows x 16B). Non-trans b16: lane gets word (lane&3) of row (lane>>2)
// per matrix -> exactly the tf32 m16n8k8 A-fragment layout.
__device__ __forceinline__ void ldsm_a(unsigned* r, uint32_t addr) {
    asm volatile("ldmatrix.sync.aligned.m8n8.x4.shared.b16 {%0,%1,%2,%3}, [%4];"
        : "=r"(r[0]), "=r"(r[1]), "=r"(r[2]), "=r"(r[3]) : "r"(addr));
}

// ---------------------------------------------------------------------------
// Stage 1a: zero activation accumulator
// ---------------------------------------------------------------------------
__global__ void zero_shared() {
    int i = blockIdx.x * 256 + threadIdx.x;
    ((float4*)g_shared)[i] = make_float4(0.f, 0.f, 0.f, 0.f);
}

// ---------------------------------------------------------------------------
// Stage 1b: split-K SIMT GEMM  g_shared += feat @ Ws
// ---------------------------------------------------------------------------
__global__ void __launch_bounds__(256)
gemm1_splitk(const float* __restrict__ feat, const float* __restrict__ Ws) {
    __shared__ float As[64][33];
    __shared__ float Bs[32][64];
    const int tid = threadIdx.x;
    const int tx = tid & 15, ty = tid >> 4;
    const int m0 = blockIdx.x * 64, n0 = blockIdx.y * 64;
    const int kbase = blockIdx.z * 256;

    float acc[4][4];
#pragma unroll
    for (int i = 0; i < 4; i++)
#pragma unroll
        for (int j = 0; j < 4; j++) acc[i][j] = 0.f;

    const int am = tid >> 2, akq = tid & 3;
    const int bk = tid >> 3, bnq = tid & 7;

    for (int k0 = kbase; k0 < kbase + 256; k0 += 32) {
#pragma unroll
        for (int h = 0; h < 2; h++) {
            float4 v = *(const float4*)&feat[(size_t)(m0 + am) * FF + k0 + akq * 8 + h * 4];
            As[am][akq * 8 + h * 4 + 0] = v.x;
            As[am][akq * 8 + h * 4 + 1] = v.y;
            As[am][akq * 8 + h * 4 + 2] = v.z;
            As[am][akq * 8 + h * 4 + 3] = v.w;
        }
#pragma unroll
        for (int h = 0; h < 2; h++) {
            float4 v = *(const float4*)&Ws[(size_t)(k0 + bk) * HH + n0 + bnq * 8 + h * 4];
            *(float4*)&Bs[bk][bnq * 8 + h * 4] = v;
        }
        __syncthreads();
#pragma unroll 8
        for (int k = 0; k < 32; k++) {
            float4 b4 = *(const float4*)&Bs[k][tx * 4];
            float b[4] = {b4.x, b4.y, b4.z, b4.w};
#pragma unroll
            for (int i = 0; i < 4; i++) {
                float a = As[ty * 4 + i][k];
#pragma unroll
                for (int j = 0; j < 4; j++) acc[i][j] += a * b[j];
            }
        }
        __syncthreads();
    }
#pragma unroll
    for (int i = 0; i < 4; i++)
#pragma unroll
        for (int j = 0; j < 4; j++)
            atomicAdd(&g_shared[(m0 + ty * 4 + i) * HH + n0 + tx * 4 + j], acc[i][j]);
}

// ---------------------------------------------------------------------------
// Stage 1c: bias + relu + tf32 round (in place)
// ---------------------------------------------------------------------------
__global__ void bias_relu_round(const float* __restrict__ bs) {
    int i = blockIdx.x * 256 + threadIdx.x;
    float4 v = ((float4*)g_shared)[i];
    int n = (i * 4) & (HH - 1);
    const float4 b = *(const float4*)&bs[n];
    v.x = __uint_as_float(f2tf32(fmaxf(v.x + b.x, 0.f)));
    v.y = __uint_as_float(f2tf32(fmaxf(v.y + b.y, 0.f)));
    v.z = __uint_as_float(f2tf32(fmaxf(v.z + b.z, 0.f)));
    v.w = __uint_as_float(f2tf32(fmaxf(v.w + b.w, 0.f)));
    ((float4*)g_shared)[i] = v;
}

// ---------------------------------------------------------------------------
// Stage 2+3+4 fused (mma.sync tf32 + ldmatrix A + 4-stage pipeline):
//   per CTA (c, m-tile 128): h = relu(shared @ W1c + b1c) [128x256],
//   logits = h @ W2c + b2c [128x8], softmax, write.
// 512 threads, warp grid 2m x 8n, warp tile 64x32, k-step 16. grid (2, 512).
// ---------------------------------------------------------------------------
// dynamic smem layout (bytes):
//   A stages [0, 40960):      4 x (128 rows x 80B)   (16 k-floats + 16B pad)
//   B stages [40960, 108544): 4 x (16 rows x 1056B)  (264 floats/row)
//   b1s [108544, 109568)
//   W2s [109568, 117760)
// epilogue overlays:
//   hsm     [0, 67584)      = 128 x 132 floats
//   partial [67584, 83968)  = 4 x 128 x 8 floats
#define A_ST     10240
#define B_ST     16896
#define OFF_A    0
#define OFF_B    40960
#define OFF_B1S  108544
#define OFF_W2S  109568
#define SMEM_BYTES 117760

__global__ void __launch_bounds__(512, 1)
gate_fused(const float* __restrict__ W1, const float* __restrict__ b1,
           const float* __restrict__ W2, const float* __restrict__ b2,
           float* __restrict__ out, int write_logits) {
    extern __shared__ char sm[];
    const uint32_t smb = smem_u32(sm);
    const int tid  = threadIdx.x;
    const int lane = tid & 31;
    const int wid  = tid >> 5;
    const int wm   = wid >> 3;           // 0..1  (m)
    const int wn   = wid & 7;            // 0..7  (n)
    const int g    = lane >> 2;          // 0..7
    const int t4   = lane & 3;           // 0..3
    const int c    = blockIdx.y;
    const int m0   = blockIdx.x * 128;
    const float* __restrict__ W1c = W1 + (size_t)c * HH * HH2;

    float* b1s = (float*)(sm + OFF_B1S);
    float* W2s = (float*)(sm + OFF_W2S);
    if (tid < 256) b1s[tid] = b1[c * HH2 + tid];

    // ldmatrix lane base: row = wm*64 + (l&7) + ((l>>3)&1)*8, col-16B = (l>>4)&1
    const uint32_t lm_base =
        (uint32_t)((wm * 64 + (lane & 7) + ((lane >> 3) & 1) * 8) * 80
                   + ((lane >> 4) & 1) * 16);

    float acc[4][4][4];
#pragma unroll
    for (int mi = 0; mi < 4; mi++)
#pragma unroll
        for (int nj = 0; nj < 4; nj++)
#pragma unroll
            for (int v = 0; v < 4; v++) acc[mi][nj][v] = 0.f;

    auto load_tile = [&](int t, int buf) {
        const int k0 = t * 16;
        const uint32_t abase = smb + OFF_A + buf * A_ST;
        const uint32_t bbase = smb + OFF_B + buf * B_ST;
        {   // A: 128 x 16 floats = 512 x 16B, one per thread
            const int m = tid >> 2, w = tid & 3;
            cp16(abase + (uint32_t)(m * 80 + w * 16),
                 g_shared + (size_t)(m0 + m) * HH + k0 + w * 4);
        }
#pragma unroll
        for (int i = 0; i < 2; i++) {    // B: 16 x 256 floats = 1024 x 16B
            const int idx = tid + 512 * i;
            const int k = idx >> 6, n4 = idx & 63;
            cp16(bbase + (uint32_t)(k * 1056 + n4 * 16),
                 W1c + (size_t)(k0 + k) * HH2 + n4 * 4);
        }
        asm volatile("cp.async.commit_group;");
    };

    load_tile(0, 0);
    load_tile(1, 1);
    load_tile(2, 2);

    const int colb = wn * 32 + g;
    for (int t = 0; t < 32; t++) {
        const int buf = t & 3;
        if (t < 30)      asm volatile("cp.async.wait_group 2;");
        else if (t == 30) asm volatile("cp.async.wait_group 1;");
        else              asm volatile("cp.async.wait_group 0;");
        __syncthreads();

        if (t + 3 < 32) load_tile(t + 3, (t + 3) & 3);

        const uint32_t alm = smb + OFF_A + buf * A_ST + lm_base;
        const float*   Bp  = (const float*)(sm + OFF_B + buf * B_ST);

#pragma unroll
        for (int ks = 0; ks < 2; ks++) {
            unsigned af[4][4];
#pragma unroll
            for (int mi = 0; mi < 4; mi++)
                ldsm_a(af[mi], alm + (uint32_t)(mi * 1280 + ks * 32));
            unsigned bf[4][2];
#pragma unroll
            for (int nj = 0; nj < 4; nj++) {
                const int col = colb + nj * 8;
                bf[nj][0] = f2tf32(Bp[(ks * 8 + t4) * 264 + col]);
                bf[nj][1] = f2tf32(Bp[(ks * 8 + 4 + t4) * 264 + col]);
            }
#pragma unroll
            for (int mi = 0; mi < 4; mi++)
#pragma unroll
                for (int nj = 0; nj < 4; nj++)
                    mma_tf32(acc[mi][nj], af[mi], bf[nj]);
        }
    }
    __syncthreads();

    // stage W2 into smem
    {
        const float4* src = (const float4*)(W2 + (size_t)c * HH2 * EE);
        ((float4*)W2s)[tid] = src[tid];               // 512 x 16B = 2048 floats
    }

    // ---- epilogue: bias+relu via smem, logits = h @ W2 ----
    float* hsm = (float*)sm;                          // [128][132]
    const int em = tid & 127, epart = tid >> 7;       // row, col-quarter
    float acc_e[8];
#pragma unroll
    for (int e = 0; e < 8; e++) acc_e[e] = 0.f;

#pragma unroll
    for (int half = 0; half < 2; half++) {
        if ((wn >> 2) == half) {
#pragma unroll
            for (int mi = 0; mi < 4; mi++) {
                const int r0 = wm * 64 + mi * 16 + g;
#pragma unroll
                for (int nj = 0; nj < 4; nj++) {
                    const int nl = (wn & 3) * 32 + nj * 8 + 2 * t4;
                    const int gn = half * 128 + nl;
                    hsm[r0 * 132 + nl]           = fmaxf(acc[mi][nj][0] + b1s[gn],     0.f);
                    hsm[r0 * 132 + nl + 1]       = fmaxf(acc[mi][nj][1] + b1s[gn + 1], 0.f);
                    hsm[(r0 + 8) * 132 + nl]     = fmaxf(acc[mi][nj][2] + b1s[gn],     0.f);
                    hsm[(r0 + 8) * 132 + nl + 1] = fmaxf(acc[mi][nj][3] + b1s[gn + 1], 0.f);
                }
            }
        }
        __syncthreads();
#pragma unroll 4
        for (int n = 0; n < 32; n++) {
            const int nl = epart * 32 + n;
            const float hv = hsm[em * 132 + nl];
            const int gn = half * 128 + nl;
            const float4 w0 = *(const float4*)&W2s[gn * 8];
            const float4 w1 = *(const float4*)&W2s[gn * 8 + 4];
            acc_e[0] += hv * w0.x; acc_e[1] += hv * w0.y;
            acc_e[2] += hv * w0.z; acc_e[3] += hv * w0.w;
            acc_e[4] += hv * w1.x; acc_e[5] += hv * w1.y;
            acc_e[6] += hv * w1.z; acc_e[7] += hv * w1.w;
        }
        __syncthreads();
    }

    // combine 4 column-quarters, softmax, write
    float* partial = (float*)(sm + 67584);            // [4][128][8]
#pragma unroll
    for (int e = 0; e < 8; e++) partial[(epart * 128 + em) * 8 + e] = acc_e[e];
    __syncthreads();

    if (tid < 128) {
        float lg[8];
        const float4 b2lo = *(const float4*)(b2 + c * 8);
        const float4 b2hi = *(const float4*)(b2 + c * 8 + 4);
#pragma unroll
        for (int e = 0; e < 8; e++) lg[e] = 0.f;
#pragma unroll
        for (int p = 0; p < 4; p++) {
            const float4 q0 = *(float4*)&partial[(p * 128 + tid) * 8];
            const float4 q1 = *(float4*)&partial[(p * 128 + tid) * 8 + 4];
            lg[0] += q0.x; lg[1] += q0.y; lg[2] += q0.z; lg[3] += q0.w;
            lg[4] += q1.x; lg[5] += q1.y; lg[6] += q1.z; lg[7] += q1.w;
        }
        lg[0] += b2lo.x; lg[1] += b2lo.y; lg[2] += b2lo.z; lg[3] += b2lo.w;
        lg[4] += b2hi.x; lg[5] += b2hi.y; lg[6] += b2hi.z; lg[7] += b2hi.w;
        float mx = lg[0];
#pragma unroll
        for (int e = 1; e < 8; e++) mx = fmaxf(mx, lg[e]);
        float w[8], s = 0.f;
#pragma unroll
        for (int e = 0; e < 8; e++) { w[e] = expf(lg[e] - mx); s += w[e]; }
        const float inv = 1.f / s;
        const size_t base = ((size_t)(m0 + tid) * CC + c) * EE;
        *(float4*)(out + base)     = make_float4(w[0]*inv, w[1]*inv, w[2]*inv, w[3]*inv);
        *(float4*)(out + base + 4) = make_float4(w[4]*inv, w[5]*inv, w[6]*inv, w[7]*inv);
        if (write_logits) {
            *(float4*)(out + BCE + base)     = make_float4(lg[0], lg[1], lg[2], lg[3]);
            *(float4*)(out + BCE + base + 4) = make_float4(lg[4], lg[5], lg[6], lg[7]);
        }
    }
}

// ---------------------------------------------------------------------------
extern "C" void kernel_launch(void* const* d_in, const int* in_sizes, int n_in,
                              void* d_out, int out_size) {
    const float* feat = (const float*)d_in[0];
    const float* Ws   = (const float*)d_in[1];
    const float* bs   = (const float*)d_in[2];
    const float* W1   = (const float*)d_in[3];
    const float* b1   = (const float*)d_in[4];
    const float* W2   = (const float*)d_in[5];
    const float* b2   = (const float*)d_in[6];
    float* out = (float*)d_out;

    zero_shared<<<128, 256>>>();
    gemm1_splitk<<<dim3(4, 8, 8), 256>>>(feat, Ws);
    bias_relu_round<<<128, 256>>>(bs);

    cudaFuncSetAttribute(gate_fused, cudaFuncAttributeMaxDynamicSharedMemorySize,
                         SMEM_BYTES);
    const int write_logits = (out_size >= 2 * BCE) ? 1 : 0;
    gate_fused<<<dim3(2, CC), 512, SMEM_BYTES>>>(W1, b1, W2, b2, out, write_logits);
}

// round 10
// speedup vs baseline: 1.2223x; 1.2223x over previous
#include <cuda_runtime.h>
#include <cuda.h>
#include <cstdint>

#define BB 256
#define FF 2048
#define HH 512
#define CC 512
#define EE 8
#define HH2 256
#define BCE (BB * CC * EE)

__device__ float g_shared[BB * HH];          // [m][k] tf32-rounded activations
__device__ float g_part[BB * CC * 2 * EE];   // [b][c][nh][e] partial logits

// ---------------------------------------------------------------------------
// helpers
// ---------------------------------------------------------------------------
__device__ __forceinline__ unsigned f2tf32(float x) {
    unsigned u; asm("cvt.rna.tf32.f32 %0, %1;" : "=r"(u) : "f"(x)); return u;
}
__device__ __forceinline__ unsigned smem_u32(const void* p) {
    return (unsigned)__cvta_generic_to_shared(p);
}
__device__ __forceinline__ void mma_tf32(float* d, const unsigned* a, const unsigned* b) {
    asm volatile(
        "mma.sync.aligned.m16n8k8.row.col.f32.tf32.tf32.f32 "
        "{%0,%1,%2,%3}, {%4,%5,%6,%7}, {%8,%9}, {%0,%1,%2,%3};"
        : "+f"(d[0]), "+f"(d[1]), "+f"(d[2]), "+f"(d[3])
        : "r"(a[0]), "r"(a[1]), "r"(a[2]), "r"(a[3]), "r"(b[0]), "r"(b[1]));
}
__device__ __forceinline__ void ldsm_a(unsigned* r, uint32_t addr) {
    asm volatile("ldmatrix.sync.aligned.m8n8.x4.shared.b16 {%0,%1,%2,%3}, [%4];"
        : "=r"(r[0]), "=r"(r[1]), "=r"(r[2]), "=r"(r[3]) : "r"(addr));
}
__device__ __forceinline__ void tma2d(uint32_t dst, const CUtensorMap* m,
                                      int x, int y, uint32_t mbar) {
    asm volatile(
        "cp.async.bulk.tensor.2d.shared::cta.global.tile.mbarrier::complete_tx::bytes "
        "[%0], [%1, {%2, %3}], [%4];"
        :: "r"(dst), "l"(m), "r"(x), "r"(y), "r"(mbar) : "memory");
}
#define MBARRIER_INIT(a, n) \
    asm volatile("mbarrier.init.shared.b64 [%0], %1;" :: "r"(a), "r"((uint32_t)(n)) : "memory")
#define MBARRIER_EXPECT_TX(a, tx) \
    asm volatile("mbarrier.arrive.expect_tx.shared.b64 _, [%0], %1;" \
                 :: "r"(a), "r"((uint32_t)(tx)) : "memory")
#define MBARRIER_WAIT_PARITY(a, par) do {                                   \
    uint32_t _m = (a), _p = (par), _done;                                   \
    asm volatile("{\n\t.reg .pred p;\n\t"                                   \
        "mbarrier.try_wait.parity.acquire.cta.shared::cta.b64 p, [%1], %2;\n\t" \
        "selp.b32 %0, 1, 0, p;\n\t}" : "=r"(_done) : "r"(_m), "r"(_p) : "memory"); \
    if (!_done) {                                                           \
        asm volatile("{\n\t.reg .pred P1;\n\t"                              \
            "WL_%=:\n\t"                                                    \
            "mbarrier.try_wait.parity.acquire.cta.shared::cta.b64 P1, [%0], %1, 0x989680;\n\t" \
            "@P1 bra.uni WD_%=;\n\t"                                        \
            "bra.uni WL_%=;\n\t"                                            \
            "WD_%=:\n\t}" :: "r"(_m), "r"(_p) : "memory");                  \
    }                                                                       \
} while (0)

// ---------------------------------------------------------------------------
// Stage 1a/1b/1c: shared = tf32(relu(feat @ Ws + bs))
// ---------------------------------------------------------------------------
__global__ void zero_shared() {
    int i = blockIdx.x * 256 + threadIdx.x;
    ((float4*)g_shared)[i] = make_float4(0.f, 0.f, 0.f, 0.f);
}

__global__ void __launch_bounds__(256)
gemm1_splitk(const float* __restrict__ feat, const float* __restrict__ Ws) {
    __shared__ float As[64][33];
    __shared__ float Bs[32][64];
    const int tid = threadIdx.x;
    const int tx = tid & 15, ty = tid >> 4;
    const int m0 = blockIdx.x * 64, n0 = blockIdx.y * 64;
    const int kbase = blockIdx.z * 256;

    float acc[4][4];
#pragma unroll
    for (int i = 0; i < 4; i++)
#pragma unroll
        for (int j = 0; j < 4; j++) acc[i][j] = 0.f;

    const int am = tid >> 2, akq = tid & 3;
    const int bk = tid >> 3, bnq = tid & 7;

    for (int k0 = kbase; k0 < kbase + 256; k0 += 32) {
#pragma unroll
        for (int h = 0; h < 2; h++) {
            float4 v = *(const float4*)&feat[(size_t)(m0 + am) * FF + k0 + akq * 8 + h * 4];
            As[am][akq * 8 + h * 4 + 0] = v.x;
            As[am][akq * 8 + h * 4 + 1] = v.y;
            As[am][akq * 8 + h * 4 + 2] = v.z;
            As[am][akq * 8 + h * 4 + 3] = v.w;
        }
#pragma unroll
        for (int h = 0; h < 2; h++) {
            float4 v = *(const float4*)&Ws[(size_t)(k0 + bk) * HH + n0 + bnq * 8 + h * 4];
            *(float4*)&Bs[bk][bnq * 8 + h * 4] = v;
        }
        __syncthreads();
#pragma unroll 8
        for (int k = 0; k < 32; k++) {
            float4 b4 = *(const float4*)&Bs[k][tx * 4];
            float b[4] = {b4.x, b4.y, b4.z, b4.w};
#pragma unroll
            for (int i = 0; i < 4; i++) {
                float a = As[ty * 4 + i][k];
#pragma unroll
                for (int j = 0; j < 4; j++) acc[i][j] += a * b[j];
            }
        }
        __syncthreads();
    }
#pragma unroll
    for (int i = 0; i < 4; i++)
#pragma unroll
        for (int j = 0; j < 4; j++)
            atomicAdd(&g_shared[(m0 + ty * 4 + i) * HH + n0 + tx * 4 + j], acc[i][j]);
}

__global__ void bias_relu_round(const float* __restrict__ bs) {
    int i = blockIdx.x * 256 + threadIdx.x;
    float4 v = ((float4*)g_shared)[i];
    int n = (i * 4) & (HH - 1);
    const float4 b = *(const float4*)&bs[n];
    v.x = __uint_as_float(f2tf32(fmaxf(v.x + b.x, 0.f)));
    v.y = __uint_as_float(f2tf32(fmaxf(v.y + b.y, 0.f)));
    v.z = __uint_as_float(f2tf32(fmaxf(v.z + b.z, 0.f)));
    v.w = __uint_as_float(f2tf32(fmaxf(v.w + b.w, 0.f)));
    ((float4*)g_shared)[i] = v;
}

// ---------------------------------------------------------------------------
// Stage 2+3 fused (mma.sync tf32, TMA + mbarrier 3-stage pipeline):
// CTA (nh, c): D[256m x 128n] = shared @ W1c[:, nh*128 + ...]
//   h = relu(D + b1 chunk); partial[m][e] = h @ W2 chunk -> g_part.
// 512 threads, warps 4m x 4n, warp tile 64x32, k-tile 32. grid (2, 512).
// smem: 3 stages x 48KB (A 32KB SW128 + B 4x4KB SW128)
//   mbar[3] @147456, b1s(128f) @147488, W2s(1024f) @148000 -> total 152096
// epilogue overlays: hsm 128x133f @0, psm 4x128x8f @68096
// ---------------------------------------------------------------------------
#define ST_SZ    49152
#define OFF_MBAR 147456
#define OFF_B1S  147488
#define OFF_W2S  148000
#define SMEM_BYTES 152096
#define HS 133

__global__ void __launch_bounds__(512, 1)
gate_fused(const __grid_constant__ CUtensorMap tmA,
           const __grid_constant__ CUtensorMap tmB,
           const float* __restrict__ b1, const float* __restrict__ W2) {
    extern __shared__ __align__(1024) char sm[];
    const uint32_t smb = smem_u32(sm);
    const int tid  = threadIdx.x;
    const int lane = tid & 31;
    const int wid  = tid >> 5;
    const int wm   = wid >> 2;           // 0..3 (m, 64 rows each)
    const int wn   = wid & 3;            // 0..3 (n, 32 cols each)
    const int g    = lane >> 2;          // 0..7
    const int t4   = lane & 3;           // 0..3
    const int r8   = lane & 7;
    const int j2   = (lane >> 4) & 1;
    const int nh   = blockIdx.x;         // n-half (0,1)
    const int c    = blockIdx.y;         // class

    float* b1s = (float*)(sm + OFF_B1S);
    float* W2s = (float*)(sm + OFF_W2S);
    if (tid < 128) b1s[tid] = b1[c * HH2 + nh * 128 + tid];
    if (tid < 256)
        ((float4*)W2s)[tid] =
            ((const float4*)(W2 + (size_t)c * HH2 * EE + nh * 128 * EE))[tid];

    if (tid == 0) {
#pragma unroll
        for (int s = 0; s < 3; s++) MBARRIER_INIT(smb + OFF_MBAR + s * 8, 1);
    }
    __syncthreads();

    auto arm = [&](int t) {
        const int s = t % 3;
        const uint32_t mb = smb + OFF_MBAR + s * 8;
        MBARRIER_EXPECT_TX(mb, ST_SZ);
        const uint32_t ab = smb + s * ST_SZ;
        tma2d(ab, &tmA, t * 32, 0, mb);                       // A: 32k x 256m
#pragma unroll
        for (int bi = 0; bi < 4; bi++)
            tma2d(ab + 32768 + bi * 4096, &tmB,
                  nh * 128 + bi * 32, c * 512 + t * 32, mb);  // B: 32n x 32k
    };
    if (tid == 0) { arm(0); arm(1); arm(2); }

    // ldmatrix per-lane row base (bytes within A stage)
    const uint32_t lmA = (uint32_t)((wm * 64 + ((lane >> 3) & 1) * 8 + r8) * 128);

    float acc[4][4][4];
#pragma unroll
    for (int mi = 0; mi < 4; mi++)
#pragma unroll
        for (int nj = 0; nj < 4; nj++)
#pragma unroll
            for (int v = 0; v < 4; v++) acc[mi][nj][v] = 0.f;

    int s = 0, ph = 0;
    for (int t = 0; t < 16; t++) {
        MBARRIER_WAIT_PARITY(smb + OFF_MBAR + s * 8, (uint32_t)ph);
        const uint32_t aoff = (uint32_t)(s * ST_SZ);
        const uint32_t boff = aoff + 32768;

#pragma unroll
        for (int ks = 0; ks < 4; ks++) {
            unsigned af[4][4];
            const uint32_t asw = (uint32_t)(((2 * ks + j2) ^ r8) << 4);
#pragma unroll
            for (int mi = 0; mi < 4; mi++)
                ldsm_a(af[mi], smb + aoff + lmA + (uint32_t)(mi * 2048) + asw);
            unsigned bf[4][2];
#pragma unroll
            for (int nj = 0; nj < 4; nj++) {
                const int nloc = nj * 8 + g;              // 0..31 in this warp's subtile
                const int c0 = nloc >> 2;                 // 16B chunk 0..7
                const int kr0 = ks * 8 + t4;
                const int kr1 = kr0 + 4;
                const uint32_t base = boff + (uint32_t)(wn * 4096 + (nloc & 3) * 4);
                const uint32_t o0 = base + (uint32_t)(kr0 * 128) +
                                    (uint32_t)(((c0 ^ (kr0 & 7)) << 4));
                const uint32_t o1 = base + (uint32_t)(kr1 * 128) +
                                    (uint32_t)(((c0 ^ (kr1 & 7)) << 4));
                bf[nj][0] = f2tf32(*(const float*)(sm + o0));
                bf[nj][1] = f2tf32(*(const float*)(sm + o1));
            }
#pragma unroll
            for (int mi = 0; mi < 4; mi++)
#pragma unroll
                for (int nj = 0; nj < 4; nj++)
                    mma_tf32(acc[mi][nj], af[mi], bf[nj]);
        }
        __syncthreads();
        if (tid == 0 && t + 3 < 16) arm(t + 3);
        if (++s == 3) { s = 0; ph ^= 1; }
    }

    // ---- epilogue: two 128-row phases; bias+relu -> hsm; partial = h @ W2 ----
    float* hsm = (float*)sm;                  // [128][HS]
    float* psm = (float*)(sm + 68096);        // [4][128][8]
    const int erow = tid & 127, eq = tid >> 7;

#pragma unroll
    for (int p = 0; p < 2; p++) {
        if ((wm >> 1) == p) {
            const int lr = (wm & 1) * 64;
#pragma unroll
            for (int mi = 0; mi < 4; mi++) {
                const int r0 = lr + mi * 16 + g;
#pragma unroll
                for (int nj = 0; nj < 4; nj++) {
                    const int nl = wn * 32 + nj * 8 + 2 * t4;
                    hsm[r0 * HS + nl]           = fmaxf(acc[mi][nj][0] + b1s[nl],     0.f);
                    hsm[r0 * HS + nl + 1]       = fmaxf(acc[mi][nj][1] + b1s[nl + 1], 0.f);
                    hsm[(r0 + 8) * HS + nl]     = fmaxf(acc[mi][nj][2] + b1s[nl],     0.f);
                    hsm[(r0 + 8) * HS + nl + 1] = fmaxf(acc[mi][nj][3] + b1s[nl + 1], 0.f);
                }
            }
        }
        __syncthreads();

        float acc_e[8];
#pragma unroll
        for (int e = 0; e < 8; e++) acc_e[e] = 0.f;
#pragma unroll 4
        for (int n = 0; n < 32; n++) {
            const int nl = eq * 32 + n;
            const float hv = hsm[erow * HS + nl];
            const float4 w0 = *(const float4*)&W2s[nl * 8];
            const float4 w1 = *(const float4*)&W2s[nl * 8 + 4];
            acc_e[0] += hv * w0.x; acc_e[1] += hv * w0.y;
            acc_e[2] += hv * w0.z; acc_e[3] += hv * w0.w;
            acc_e[4] += hv * w1.x; acc_e[5] += hv * w1.y;
            acc_e[6] += hv * w1.z; acc_e[7] += hv * w1.w;
        }
#pragma unroll
        for (int e = 0; e < 8; e++) psm[(eq * 128 + erow) * 8 + e] = acc_e[e];
        __syncthreads();

        if (tid < 128) {
            float4 s0 = *(float4*)&psm[tid * 8];
            float4 s1 = *(float4*)&psm[tid * 8 + 4];
#pragma unroll
            for (int q = 1; q < 4; q++) {
                float4 q0 = *(float4*)&psm[(q * 128 + tid) * 8];
                float4 q1 = *(float4*)&psm[(q * 128 + tid) * 8 + 4];
                s0.x += q0.x; s0.y += q0.y; s0.z += q0.z; s0.w += q0.w;
                s1.x += q1.x; s1.y += q1.y; s1.z += q1.z; s1.w += q1.w;
            }
            const int m = p * 128 + tid;
            float* dst = &g_part[(((size_t)m * CC + c) * 2 + nh) * EE];
            *(float4*)(dst + 0) = s0;
            *(float4*)(dst + 4) = s1;
        }
        __syncthreads();
    }
}

// ---------------------------------------------------------------------------
// Stage 4: combine n-halves, + b2, softmax over E=8, write (weights, logits)
// ---------------------------------------------------------------------------
__global__ void softmax_out(const float* __restrict__ b2,
                            float* __restrict__ out, int write_logits) {
    const int idx = blockIdx.x * 256 + threadIdx.x;   // b*CC + c
    const int c = idx & (CC - 1);
    const float4* pp = (const float4*)&g_part[(size_t)idx * 16];
    const float4 a0 = pp[0], a1 = pp[1], a2 = pp[2], a3 = pp[3];
    float lg[8];
    lg[0] = a0.x + a2.x; lg[1] = a0.y + a2.y; lg[2] = a0.z + a2.z; lg[3] = a0.w + a2.w;
    lg[4] = a1.x + a3.x; lg[5] = a1.y + a3.y; lg[6] = a1.z + a3.z; lg[7] = a1.w + a3.w;
    float mx = -1e30f;
#pragma unroll
    for (int e = 0; e < 8; e++) { lg[e] += b2[c * EE + e]; mx = fmaxf(mx, lg[e]); }
    float w[8], s = 0.f;
#pragma unroll
    for (int e = 0; e < 8; e++) { w[e] = expf(lg[e] - mx); s += w[e]; }
    const float inv = 1.f / s;
    const size_t base = (size_t)idx * 8;
    *(float4*)(out + base)     = make_float4(w[0]*inv, w[1]*inv, w[2]*inv, w[3]*inv);
    *(float4*)(out + base + 4) = make_float4(w[4]*inv, w[5]*inv, w[6]*inv, w[7]*inv);
    if (write_logits) {
        *(float4*)(out + BCE + base)     = make_float4(lg[0], lg[1], lg[2], lg[3]);
        *(float4*)(out + BCE + base + 4) = make_float4(lg[4], lg[5], lg[6], lg[7]);
    }
}

// ---------------------------------------------------------------------------
typedef CUresult (*PFN_tmap_encode)(
    CUtensorMap*, CUtensorMapDataType, cuuint32_t, void*,
    const cuuint64_t*, const cuuint64_t*, const cuuint32_t*, const cuuint32_t*,
    CUtensorMapInterleave, CUtensorMapSwizzle, CUtensorMapL2promotion,
    CUtensorMapFloatOOBfill);

extern "C" void kernel_launch(void* const* d_in, const int* in_sizes, int n_in,
                              void* d_out, int out_size) {
    const float* feat = (const float*)d_in[0];
    const float* Ws   = (const float*)d_in[1];
    const float* bs   = (const float*)d_in[2];
    const float* W1   = (const float*)d_in[3];
    const float* b1   = (const float*)d_in[4];
    const float* W2   = (const float*)d_in[5];
    const float* b2   = (const float*)d_in[6];
    float* out = (float*)d_out;

    zero_shared<<<128, 256>>>();
    gemm1_splitk<<<dim3(4, 8, 8), 256>>>(feat, Ws);
    bias_relu_round<<<128, 256>>>(bs);

    // ---- build tensormaps (host-side, allocation-free, capture-safe) ----
    PFN_tmap_encode enc = nullptr;
    cudaDriverEntryPointQueryResult qres;
    cudaGetDriverEntryPointByVersion("cuTensorMapEncodeTiled", (void**)&enc,
                                     12000, cudaEnableDefault, &qres);
    void* shared_ptr = nullptr;
    cudaGetSymbolAddress(&shared_ptr, g_shared);

    CUtensorMap tmA{}, tmB{};
    {
        cuuint64_t dims[2]    = {HH, BB};           // inner k=512, m=256
        cuuint64_t strides[1] = {HH * 4};           // 2048 B/row
        cuuint32_t box[2]     = {32, 256};          // 32k x 256m
        cuuint32_t es[2]      = {1, 1};
        enc(&tmA, CU_TENSOR_MAP_DATA_TYPE_FLOAT32, 2, shared_ptr,
            dims, strides, box, es,
            CU_TENSOR_MAP_INTERLEAVE_NONE, CU_TENSOR_MAP_SWIZZLE_128B,
            CU_TENSOR_MAP_L2_PROMOTION_L2_128B, CU_TENSOR_MAP_FLOAT_OOB_FILL_NONE);
    }
    {
        cuuint64_t dims[2]    = {HH2, (cuuint64_t)CC * HH}; // inner n=256, rows c*k
        cuuint64_t strides[1] = {HH2 * 4};                  // 1024 B/row
        cuuint32_t box[2]     = {32, 32};                   // 32n x 32k
        cuuint32_t es[2]      = {1, 1};
        enc(&tmB, CU_TENSOR_MAP_DATA_TYPE_FLOAT32, 2, (void*)W1,
            dims, strides, box, es,
            CU_TENSOR_MAP_INTERLEAVE_NONE, CU_TENSOR_MAP_SWIZZLE_128B,
            CU_TENSOR_MAP_L2_PROMOTION_L2_128B, CU_TENSOR_MAP_FLOAT_OOB_FILL_NONE);
    }

    cudaFuncSetAttribute(gate_fused, cudaFuncAttributeMaxDynamicSharedMemorySize,
                         SMEM_BYTES);
    gate_fused<<<dim3(2, CC), 512, SMEM_BYTES>>>(tmA, tmB, b1, W2);

    const int write_logits = (out_size >= 2 * BCE) ? 1 : 0;
    softmax_out<<<BB * CC / 256, 256>>>(b2, out, write_logits);
}